// round 15
// baseline (speedup 1.0000x reference)
#include <cuda_runtime.h>

#define NQ    20
#define NPART 10
#define NB    294          // blocks; 4 columns each; 2 blocks/SM on 147 SMs
#define CPB   4
#define TPB   512          // 16 warps = 4 quads

__device__ __forceinline__ float2 cmul(float2 a, float2 b) {
    return make_float2(a.x * b.x - a.y * b.y, a.x * b.y + a.y * b.x);
}
__device__ __forceinline__ float2 cadd(float2 a, float2 b) {
    return make_float2(a.x + b.x, a.y + b.y);
}

// explicit-FMA 2x2 complex butterfly; gates packed (V00,V01)=G01, (V10,V11)=G23
__device__ __forceinline__ void bfly4(float2& A0, float2& A1, float4 G01, float4 G23) {
    float a0x = A0.x, a0y = A0.y, a1x = A1.x, a1y = A1.y;
    float r0 =  G01.x * a0x;
    r0 = fmaf(-G01.y, a0y, r0);
    r0 = fmaf( G01.z, a1x, r0);
    r0 = fmaf(-G01.w, a1y, r0);
    float i0 =  G01.x * a0y;
    i0 = fmaf( G01.y, a0x, i0);
    i0 = fmaf( G01.z, a1y, i0);
    i0 = fmaf( G01.w, a1x, i0);
    float r1 =  G23.x * a0x;
    r1 = fmaf(-G23.y, a0y, r1);
    r1 = fmaf( G23.z, a1x, r1);
    r1 = fmaf(-G23.w, a1y, r1);
    float i1 =  G23.x * a0y;
    i1 = fmaf( G23.y, a0x, i1);
    i1 = fmaf( G23.z, a1y, i1);
    i1 = fmaf( G23.w, a1x, i1);
    A0 = make_float2(r0, i0);
    A1 = make_float2(r1, i1);
}

// explicit-FMA update A = Vs*A + Vo*O
__device__ __forceinline__ float2 bmix(float2 A, float2 O, float2 Vs, float2 Vo) {
    float r =  Vs.x * A.x;
    r = fmaf(-Vs.y, A.y, r);
    r = fmaf( Vo.x, O.x, r);
    r = fmaf(-Vo.y, O.y, r);
    float i =  Vs.x * A.y;
    i = fmaf( Vs.y, A.x, i);
    i = fmaf( Vo.x, O.y, i);
    i = fmaf( Vo.y, O.x, i);
    return make_float2(r, i);
}

// ---------------------------------------------------------------------------
// 294 blocks x 512 threads (2 blocks/SM); each 4-warp QUAD owns one column.
// 8 float2 amps/thread, h = (qw<<8)|(lane<<3)|r:
//   3 reg stages (gates 9,8,7) -> 5 shfl stages (gates 6..2) ->
//   interleaved-float2 swizzled exchange -> 2 reg stages (gates 1,0) ->
//   |amp|^2 pairs into 512-slot plane -> tail: 1 iter/thread, RED into out.
// ---------------------------------------------------------------------------
__global__ void __launch_bounds__(TPB, 2) sim_kernel(const float* __restrict__ x,
                                                     const float* __restrict__ w,
                                                     float* __restrict__ out) {
    extern __shared__ float2 dyn2[];
    float2* sT1 = dyn2;            // [1024] (overlaid by staging later)
    float2* sT2 = dyn2 + 1024;     // [1024]
    // staging: column c -> float2 plane dyn2 + c*1024

    __shared__ float2 sv[NQ][2];
    __shared__ int    sFB[NQ];
    __shared__ float4 sV4[20];     // gate q: [2q]=(V00,V01), [2q+1]=(V10,V11)
    __shared__ int    sXR[8];

    const int tid  = threadIdx.x;
    const int warp = tid >> 5;
    const int lane = tid & 31;
    const int c    = warp >> 2;        // column slot 0..3
    const int qw   = warp & 3;         // warp-in-quad (h bits 8,9)

    const float RS2  = 0.70710678118654752440f;   // 1/sqrt(2)
    const float WMUL = 0.63245553203367586640f;   // sqrt(2/5)

    if (tid < NQ) {
        // encoding column v_q = Rz(atan(x^2)) * Ry(atan(x)) * H |0>
        const int q = tid;
        float xq = x[q];
        float th = atanf(xq);
        float cc, ss;
        sincosf(0.5f * th, &ss, &cc);
        float a = (cc - ss) * RS2;
        float b = (cc + ss) * RS2;
        float ph = 0.5f * atanf(xq * xq);
        float pc, ps;
        sincosf(ph, &ps, &pc);
        sv[q][0] = make_float2(a * pc, -a * ps);
        sv[q][1] = make_float2(b * pc,  b * ps);

        // f = inverse CNOT-ring permutation on basis bit p=tid
        int y = 1 << tid;
        for (int qq = NQ - 1; qq >= 0; --qq) {
            int cb  = 19 - qq;
            int tb2 = 19 - ((qq + 2) % NQ);
            int tb1 = 19 - ((qq + 1) % NQ);
            if ((y >> cb) & 1) y ^= (1 << tb2);
            if ((y >> cb) & 1) y ^= (1 << tb1);
        }
        sFB[tid] = y;
    }

    if (tid < NPART) {
        // fused variational gate V = Rx(w2) * Rz(w1) * Rx(w0), measured qubits
        const int q = tid;
        float w0 = w[3 * q + 0] * WMUL;
        float w1 = w[3 * q + 1] * WMUL;
        float w2 = w[3 * q + 2] * WMUL;
        float c0, s0, c1, s1, c2, s2;
        sincosf(0.5f * w0, &s0, &c0);
        sincosf(0.5f * w1, &s1, &c1);
        sincosf(0.5f * w2, &s2, &c2);
        float2 r00 = make_float2(c0, 0.f), r01 = make_float2(0.f, -s0);
        float2 d0  = make_float2(c1, -s1), d1  = make_float2(c1,  s1);
        float2 A00 = cmul(d0, r00), A01 = cmul(d0, r01);
        float2 A10 = cmul(d1, r01), A11 = cmul(d1, r00);
        float2 m = make_float2(0.f, -s2);
        float2 V00 = cadd(make_float2(c2 * A00.x, c2 * A00.y), cmul(m, A10));
        float2 V01 = cadd(make_float2(c2 * A01.x, c2 * A01.y), cmul(m, A11));
        float2 V10 = cadd(cmul(m, A00), make_float2(c2 * A10.x, c2 * A10.y));
        float2 V11 = cadd(cmul(m, A01), make_float2(c2 * A11.x, c2 * A11.y));
        sV4[2 * q + 0] = make_float4(V00.x, V00.y, V01.x, V01.y);
        sV4[2 * q + 1] = make_float4(V10.x, V10.y, V11.x, V11.y);
    }
    __syncthreads();

    // product tables (2 entries/thread)
    for (int a = tid; a < 1024; a += TPB) {
        float2 p1 = make_float2(1.f, 0.f);
        float2 p2 = make_float2(1.f, 0.f);
#pragma unroll
        for (int q = 0; q < NPART; ++q)
            p1 = cmul(p1, sv[q][(a >> (9 - q)) & 1]);
#pragma unroll
        for (int q = NPART; q < NQ; ++q)
            p2 = cmul(p2, sv[q][(a >> (19 - q)) & 1]);
        sT1[a] = p1;
        sT2[a] = p2;
    }
    if (tid < 8) {
        int v = 0;
#pragma unroll
        for (int i = 0; i < 3; ++i)
            if ((tid >> i) & 1) v ^= sFB[10 + i];   // h bit i -> global bit 10+i
        sXR[tid] = v;
    }
    __syncthreads();

    // ---- this quad's column (dummy slots masked via wgt)
    const int lraw = blockIdx.x * CPB + c;
    const float wgt = (lraw < 1024) ? 1.f : 0.f;
    const int l = lraw & 1023;
    int xl = 0;
#pragma unroll
    for (int j = 0; j < 10; ++j)
        if ((l >> j) & 1) xl ^= sFB[j];
    int hx = 0;
#pragma unroll
    for (int p = 0; p < 5; ++p)
        if ((lane >> p) & 1) hx ^= sFB[13 + p];   // h bit 3+p -> global bit 13+p
    if (qw & 1) hx ^= sFB[18];                    // h bit 8
    if (qw & 2) hx ^= sFB[19];                    // h bit 9
    const int xbase = xl ^ hx;

    // synthesize 8 amps: h = (qw<<8)|(lane<<3)|r
    float2 a[8];
#pragma unroll
    for (int r = 0; r < 8; ++r) {
        int xx = xbase ^ sXR[r];
        a[r] = cmul(sT1[xx >> 10], sT2[xx & 1023]);
    }
    __syncthreads();   // all warps done reading tables -> staging may overwrite

    // phase 1: 3 register stages on h bits 0..2 (gates q = 9,8,7)
#pragma unroll
    for (int b = 0; b < 3; ++b) {
        const int q = 9 - b;
        float4 G01 = sV4[2 * q], G23 = sV4[2 * q + 1];
#pragma unroll
        for (int g = 0; g < 4; ++g) {
            int lo = g & ((1 << b) - 1);
            int r0 = ((g >> b) << (b + 1)) | lo;
            int r1 = r0 | (1 << b);
            bfly4(a[r0], a[r1], G01, G23);
        }
    }

    // phase 2: 5 shfl stages on h bits 3..7 (lane bit p, gates q = 6..2)
#pragma unroll
    for (int p = 0; p < 5; ++p) {
        const int q = 6 - p;
        float4 G01 = sV4[2 * q], G23 = sV4[2 * q + 1];
        const int bitv = (lane >> p) & 1;
        const float2 Vs = bitv ? make_float2(G23.z, G23.w) : make_float2(G01.x, G01.y);
        const float2 Vo = bitv ? make_float2(G23.x, G23.y) : make_float2(G01.z, G01.w);
#pragma unroll
        for (int r = 0; r < 8; ++r) {
            float2 o;
            o.x = __shfl_xor_sync(0xffffffffu, a[r].x, 1 << p);
            o.y = __shfl_xor_sync(0xffffffffu, a[r].y, 1 << p);
            a[r] = bmix(a[r], o, Vs, Vo);
        }
    }

    // exchange through interleaved float2 plane, swizzle ad(h) = h ^ ((h>>3)&15).
    // store: h = (qw<<8)|(lane<<3)|r -> ad = stb ^ r (XOR: r disjoint from base)
    float2* pl = dyn2 + c * 1024;
    {
        const int stb = ((qw << 8) | (lane << 3)) ^ (lane & 15);
#pragma unroll
        for (int r = 0; r < 8; ++r)
            pl[stb ^ r] = a[r];
    }
    asm volatile("bar.sync %0, %1;" :: "r"(c + 1), "r"(128) : "memory");

    // read: h = ((r&3)<<8)|(lane<<3)|(qw<<1)|(r>>2); mask = lane&15
    {
        const int sbase = ((lane << 3) | (qw << 1)) ^ (lane & 15);
#pragma unroll
        for (int r = 0; r < 8; ++r)
            a[r] = pl[sbase ^ ((r & 3) << 8) ^ (r >> 2)];
    }
    // all exchange reads must complete before p-pairs overwrite the plane
    asm volatile("bar.sync %0, %1;" :: "r"(c + 1), "r"(128) : "memory");

    // phase 3: 2 register stages on h bit 8 (gate 1, r bit0), h bit 9 (gate 0, r bit1)
    {
        float4 G01 = sV4[2], G23 = sV4[3];     // gate 1
        bfly4(a[0], a[1], G01, G23);
        bfly4(a[2], a[3], G01, G23);
        bfly4(a[4], a[5], G01, G23);
        bfly4(a[6], a[7], G01, G23);
    }
    {
        float4 G01 = sV4[0], G23 = sV4[1];     // gate 0
        bfly4(a[0], a[2], G01, G23);
        bfly4(a[1], a[3], G01, G23);
        bfly4(a[4], a[6], G01, G23);
        bfly4(a[5], a[7], G01, G23);
    }

    // |amp|^2 pairs: h(r) and h(r)|1 = (r, r+4); slot i = h>>1, pd = i ^ ((i>>4)&15)
#pragma unroll
    for (int r = 0; r < 4; ++r) {
        float p0 = a[r].x * a[r].x;
        p0 = fmaf(a[r].y, a[r].y, p0);
        float p1 = a[r + 4].x * a[r + 4].x;
        p1 = fmaf(a[r + 4].y, a[r + 4].y, p1);
        int i = (r << 7) | (lane << 2) | qw;
        int pd = i ^ ((i >> 4) & 15);
        pl[pd] = make_float2(wgt * p0, wgt * p1);
    }
    __syncthreads();

    // tail: one h-pair per thread across the 4 columns, RED into out
    {
        const int i  = tid;                        // 0..511
        const int pd = i ^ ((i >> 4) & 15);
        float2 s = make_float2(0.f, 0.f);
#pragma unroll
        for (int cc = 0; cc < CPB; ++cc) {
            float2 v = dyn2[cc * 1024 + pd];
            s.x += v.x;
            s.y += v.y;
        }
        atomicAdd(&out[2 * i],     s.x);
        atomicAdd(&out[2 * i + 1], s.y);
    }
}

extern "C" void kernel_launch(void* const* d_in, const int* in_sizes, int n_in,
                              void* d_out, int out_size) {
    const float* x = (const float*)d_in[0];   // (1, 20) float32
    const float* w = (const float*)d_in[1];   // (60,)  float32
    float* out = (float*)d_out;               // (1, 1024) float32

    cudaMemsetAsync(out, 0, 1024 * sizeof(float));
    const int dynsmem = CPB * 1024 * sizeof(float2);   // 32 KB (tables overlay staging)
    cudaFuncSetAttribute(sim_kernel, cudaFuncAttributeMaxDynamicSharedMemorySize, dynsmem);
    sim_kernel<<<NB, TPB, dynsmem>>>(x, w, out);
}

// round 16
// speedup vs baseline: 1.1224x; 1.1224x over previous
#include <cuda_runtime.h>

#define NQ    20
#define NPART 10
#define NB    147          // blocks; 7 columns each, 4-warp quad per column
#define CPB   7
#define TPB   (CPB * 128)  // 896 threads = 28 warps

__device__ __forceinline__ float2 cmul(float2 a, float2 b) {
    return make_float2(a.x * b.x - a.y * b.y, a.x * b.y + a.y * b.x);
}
__device__ __forceinline__ float2 cadd(float2 a, float2 b) {
    return make_float2(a.x + b.x, a.y + b.y);
}

// explicit-FMA 2x2 complex butterfly; gates packed (V00,V01)=G01, (V10,V11)=G23
__device__ __forceinline__ void bfly4(float2& A0, float2& A1, float4 G01, float4 G23) {
    float a0x = A0.x, a0y = A0.y, a1x = A1.x, a1y = A1.y;
    float r0 =  G01.x * a0x;
    r0 = fmaf(-G01.y, a0y, r0);
    r0 = fmaf( G01.z, a1x, r0);
    r0 = fmaf(-G01.w, a1y, r0);
    float i0 =  G01.x * a0y;
    i0 = fmaf( G01.y, a0x, i0);
    i0 = fmaf( G01.z, a1y, i0);
    i0 = fmaf( G01.w, a1x, i0);
    float r1 =  G23.x * a0x;
    r1 = fmaf(-G23.y, a0y, r1);
    r1 = fmaf( G23.z, a1x, r1);
    r1 = fmaf(-G23.w, a1y, r1);
    float i1 =  G23.x * a0y;
    i1 = fmaf( G23.y, a0x, i1);
    i1 = fmaf( G23.z, a1y, i1);
    i1 = fmaf( G23.w, a1x, i1);
    A0 = make_float2(r0, i0);
    A1 = make_float2(r1, i1);
}

// explicit-FMA update A = Vs*A + Vo*O
__device__ __forceinline__ float2 bmix(float2 A, float2 O, float2 Vs, float2 Vo) {
    float r =  Vs.x * A.x;
    r = fmaf(-Vs.y, A.y, r);
    r = fmaf( Vo.x, O.x, r);
    r = fmaf(-Vo.y, O.y, r);
    float i =  Vs.x * A.y;
    i = fmaf( Vs.y, A.x, i);
    i = fmaf( Vo.x, O.y, i);
    i = fmaf( Vo.y, O.x, i);
    return make_float2(r, i);
}

// ---------------------------------------------------------------------------
// 147 blocks x 896 threads; each 4-warp QUAD owns one column l (7/block).
// 8 float2 amps/thread, h = (qw<<8)|(lane<<3)|r:
//   3 reg stages (gates 9,8,7) -> 5 shfl stages (gates 6..2) ->
//   float2-interleaved exchange, swizzle ad(h) = h ^ ((h>>3)&15) ->
//   2 reg stages (gates 1,0) -> |amp|^2 h-pairs into own slots ->
//   tail: tid<512, 7x LDS.64 + 2 REDs into out (after memset node).
// ---------------------------------------------------------------------------
__global__ void __launch_bounds__(TPB, 1) sim_kernel(const float* __restrict__ x,
                                                     const float* __restrict__ w,
                                                     float* __restrict__ out) {
    extern __shared__ float2 dyn2[];
    float2* sT1 = dyn2;            // [1024] (overlaid by staging later)
    float2* sT2 = dyn2 + 1024;     // [1024]
    // staging: column c -> float2 plane dyn2 + c*1024

    __shared__ float2 sv[NQ][2];
    __shared__ int    sFB[NQ];
    __shared__ float4 sV4[20];     // gate q: [2q]=(V00,V01), [2q+1]=(V10,V11)
    __shared__ int    sXR[8];

    const int tid  = threadIdx.x;
    const int warp = tid >> 5;
    const int lane = tid & 31;
    const int c    = warp >> 2;        // column slot 0..6
    const int qw   = warp & 3;         // warp-in-quad (h bits 8,9)

    const float RS2  = 0.70710678118654752440f;   // 1/sqrt(2)
    const float WMUL = 0.63245553203367586640f;   // sqrt(2/5)

    if (tid < NQ) {
        // encoding column v_q = Rz(atan(x^2)) * Ry(atan(x)) * H |0>
        const int q = tid;
        float xq = x[q];
        float th = atanf(xq);
        float cc, ss;
        sincosf(0.5f * th, &ss, &cc);
        float a = (cc - ss) * RS2;
        float b = (cc + ss) * RS2;
        float ph = 0.5f * atanf(xq * xq);
        float pc, ps;
        sincosf(ph, &ps, &pc);
        sv[q][0] = make_float2(a * pc, -a * ps);
        sv[q][1] = make_float2(b * pc,  b * ps);

        // f = inverse CNOT-ring permutation on basis bit p=tid
        int y = 1 << tid;
        for (int qq = NQ - 1; qq >= 0; --qq) {
            int cb  = 19 - qq;
            int tb2 = 19 - ((qq + 2) % NQ);
            int tb1 = 19 - ((qq + 1) % NQ);
            if ((y >> cb) & 1) y ^= (1 << tb2);
            if ((y >> cb) & 1) y ^= (1 << tb1);
        }
        sFB[tid] = y;
    }

    if (tid < NPART) {
        // fused variational gate V = Rx(w2) * Rz(w1) * Rx(w0), measured qubits
        const int q = tid;
        float w0 = w[3 * q + 0] * WMUL;
        float w1 = w[3 * q + 1] * WMUL;
        float w2 = w[3 * q + 2] * WMUL;
        float c0, s0, c1, s1, c2, s2;
        sincosf(0.5f * w0, &s0, &c0);
        sincosf(0.5f * w1, &s1, &c1);
        sincosf(0.5f * w2, &s2, &c2);
        float2 r00 = make_float2(c0, 0.f), r01 = make_float2(0.f, -s0);
        float2 d0  = make_float2(c1, -s1), d1  = make_float2(c1,  s1);
        float2 A00 = cmul(d0, r00), A01 = cmul(d0, r01);
        float2 A10 = cmul(d1, r01), A11 = cmul(d1, r00);
        float2 m = make_float2(0.f, -s2);
        float2 V00 = cadd(make_float2(c2 * A00.x, c2 * A00.y), cmul(m, A10));
        float2 V01 = cadd(make_float2(c2 * A01.x, c2 * A01.y), cmul(m, A11));
        float2 V10 = cadd(cmul(m, A00), make_float2(c2 * A10.x, c2 * A10.y));
        float2 V11 = cadd(cmul(m, A01), make_float2(c2 * A11.x, c2 * A11.y));
        sV4[2 * q + 0] = make_float4(V00.x, V00.y, V01.x, V01.y);
        sV4[2 * q + 1] = make_float4(V10.x, V10.y, V11.x, V11.y);
    }
    __syncthreads();

    // product tables
    for (int a = tid; a < 1024; a += TPB) {
        float2 p1 = make_float2(1.f, 0.f);
        float2 p2 = make_float2(1.f, 0.f);
#pragma unroll
        for (int q = 0; q < NPART; ++q)
            p1 = cmul(p1, sv[q][(a >> (9 - q)) & 1]);
#pragma unroll
        for (int q = NPART; q < NQ; ++q)
            p2 = cmul(p2, sv[q][(a >> (19 - q)) & 1]);
        sT1[a] = p1;
        sT2[a] = p2;
    }
    if (tid < 8) {
        int v = 0;
#pragma unroll
        for (int i = 0; i < 3; ++i)
            if ((tid >> i) & 1) v ^= sFB[10 + i];   // h bit i -> global bit 10+i
        sXR[tid] = v;
    }
    __syncthreads();

    // ---- this quad's column (dummy slots masked via wgt)
    const int lraw = blockIdx.x * CPB + c;
    const float wgt = (lraw < 1024) ? 1.f : 0.f;
    const int l = lraw & 1023;
    int xl = 0;
#pragma unroll
    for (int j = 0; j < 10; ++j)
        if ((l >> j) & 1) xl ^= sFB[j];
    int hx = 0;
#pragma unroll
    for (int p = 0; p < 5; ++p)
        if ((lane >> p) & 1) hx ^= sFB[13 + p];   // h bit 3+p -> global bit 13+p
    if (qw & 1) hx ^= sFB[18];                    // h bit 8
    if (qw & 2) hx ^= sFB[19];                    // h bit 9
    const int xbase = xl ^ hx;

    // synthesize 8 amps: h = (qw<<8)|(lane<<3)|r
    float2 a[8];
#pragma unroll
    for (int r = 0; r < 8; ++r) {
        int xx = xbase ^ sXR[r];
        a[r] = cmul(sT1[xx >> 10], sT2[xx & 1023]);
    }
    __syncthreads();   // all warps done reading tables -> staging may overwrite

    // phase 1: 3 register stages on h bits 0..2 (gates q = 9,8,7)
#pragma unroll
    for (int b = 0; b < 3; ++b) {
        const int q = 9 - b;
        float4 G01 = sV4[2 * q], G23 = sV4[2 * q + 1];
#pragma unroll
        for (int g = 0; g < 4; ++g) {
            int lo = g & ((1 << b) - 1);
            int r0 = ((g >> b) << (b + 1)) | lo;
            int r1 = r0 | (1 << b);
            bfly4(a[r0], a[r1], G01, G23);
        }
    }

    // phase 2: 5 shfl stages on h bits 3..7 (lane bit p, gates q = 6..2)
#pragma unroll
    for (int p = 0; p < 5; ++p) {
        const int q = 6 - p;
        float4 G01 = sV4[2 * q], G23 = sV4[2 * q + 1];
        const int bitv = (lane >> p) & 1;
        const float2 Vs = bitv ? make_float2(G23.z, G23.w) : make_float2(G01.x, G01.y);
        const float2 Vo = bitv ? make_float2(G23.x, G23.y) : make_float2(G01.z, G01.w);
#pragma unroll
        for (int r = 0; r < 8; ++r) {
            float2 o;
            o.x = __shfl_xor_sync(0xffffffffu, a[r].x, 1 << p);
            o.y = __shfl_xor_sync(0xffffffffu, a[r].y, 1 << p);
            a[r] = bmix(a[r], o, Vs, Vo);
        }
    }

    // exchange through interleaved float2 plane; swizzle ad(h) = h ^ ((h>>3)&15)
    // store: h = (qw<<8)|(lane<<3)|r -> ad = stb ^ r (r disjoint from base)
    float2* pl = dyn2 + c * 1024;
    {
        const int stb = ((qw << 8) | (lane << 3)) ^ (lane & 15);
#pragma unroll
        for (int r = 0; r < 8; ++r)
            pl[stb ^ r] = a[r];
    }
    asm volatile("bar.sync %0, %1;" :: "r"(c + 1), "r"(128) : "memory");

    // read: h = ((r&3)<<8)|(lane<<3)|(qw<<1)|(r>>2); (h>>3)&15 = lane&15
    // cache addresses: reused by the psq-pair store (same slots, no barrier)
    int sad[8];
    {
        const int sbase = ((lane << 3) | (qw << 1)) ^ (lane & 15);
#pragma unroll
        for (int r = 0; r < 8; ++r)
            sad[r] = sbase ^ ((r & 3) << 8) ^ (r >> 2);
#pragma unroll
        for (int r = 0; r < 8; ++r)
            a[r] = pl[sad[r]];
    }

    // phase 3: 2 register stages on h bit 8 (gate 1, r bit0), h bit 9 (gate 0, r bit1)
    {
        float4 G01 = sV4[2], G23 = sV4[3];     // gate 1
        bfly4(a[0], a[1], G01, G23);
        bfly4(a[2], a[3], G01, G23);
        bfly4(a[4], a[5], G01, G23);
        bfly4(a[6], a[7], G01, G23);
    }
    {
        float4 G01 = sV4[0], G23 = sV4[1];     // gate 0
        bfly4(a[0], a[2], G01, G23);
        bfly4(a[1], a[3], G01, G23);
        bfly4(a[4], a[6], G01, G23);
        bfly4(a[5], a[7], G01, G23);
    }

    // |amp|^2 pairs: amps r and r+4 are h_even=h(r) and h_even|1.
    // Write pair into slot sad[r] — a slot THIS thread read; no barrier needed.
#pragma unroll
    for (int r = 0; r < 4; ++r) {
        float p0 = a[r].x * a[r].x;
        p0 = fmaf(a[r].y, a[r].y, p0);
        float p1 = a[r + 4].x * a[r + 4].x;
        p1 = fmaf(a[r + 4].y, a[r + 4].y, p1);
        pl[sad[r]] = make_float2(wgt * p0, wgt * p1);
    }
    __syncthreads();

    // tail: tid<512 handles h-pair i; slot(i) = (2i) ^ ((i>>2)&15)
    if (tid < 512) {
        const int i  = tid;
        const int ad = (2 * i) ^ ((i >> 2) & 15);
        float2 s = make_float2(0.f, 0.f);
#pragma unroll
        for (int cc = 0; cc < CPB; ++cc) {
            float2 v = dyn2[cc * 1024 + ad];
            s.x += v.x;
            s.y += v.y;
        }
        atomicAdd(&out[2 * i],     s.x);
        atomicAdd(&out[2 * i + 1], s.y);
    }
}

extern "C" void kernel_launch(void* const* d_in, const int* in_sizes, int n_in,
                              void* d_out, int out_size) {
    const float* x = (const float*)d_in[0];   // (1, 20) float32
    const float* w = (const float*)d_in[1];   // (60,)  float32
    float* out = (float*)d_out;               // (1, 1024) float32

    cudaMemsetAsync(out, 0, 1024 * sizeof(float));
    const int dynsmem = CPB * 1024 * sizeof(float2);   // 56 KB (tables overlay staging)
    cudaFuncSetAttribute(sim_kernel, cudaFuncAttributeMaxDynamicSharedMemorySize, dynsmem);
    sim_kernel<<<NB, TPB, dynsmem>>>(x, w, out);
}

// round 17
// speedup vs baseline: 1.4286x; 1.2727x over previous
#include <cuda_runtime.h>

#define NQ    20
#define NPART 10
#define NB    147          // blocks; 7 columns each, 4-warp quad per column
#define CPB   7
#define TPB   (CPB * 128)  // 896 threads = 28 warps

__device__ __forceinline__ float2 cmul(float2 a, float2 b) {
    return make_float2(a.x * b.x - a.y * b.y, a.x * b.y + a.y * b.x);
}
__device__ __forceinline__ float2 cadd(float2 a, float2 b) {
    return make_float2(a.x + b.x, a.y + b.y);
}

// REAL 2x2 rotation butterfly: A0' = c A0 - s A1; A1' = s A0 + c A1 (8 FMA)
__device__ __forceinline__ void bflyR(float2& A0, float2& A1, float c, float s) {
    float n0x = fmaf(-s, A1.x, c * A0.x);
    float n0y = fmaf(-s, A1.y, c * A0.y);
    float n1x = fmaf( c, A1.x, s * A0.x);
    float n1y = fmaf( c, A1.y, s * A0.y);
    A0 = make_float2(n0x, n0y);
    A1 = make_float2(n1x, n1y);
}

// bank-conflict-free bijection on 0..1023: XOR h[7:3] into h[4:0]
__device__ __forceinline__ int swz(int h) {
    return h ^ ((h >> 3) & 31);
}

// ---------------------------------------------------------------------------
// 147 blocks x 896 threads; each 4-warp QUAD owns one column l (7/block).
// Variational layer ZYZ-decomposed: diagonal Rz(gamma) phases folded into
// synthesis, Rz(alpha) dropped (global phase per amp under |.|^2), all
// butterfly stages REAL Ry rotations (half the FMA).
// 8 float2 amps/thread, h = (qw<<8)|(lane<<3)|r:
//   3 real reg stages (gates 9,8,7) -> 5 real shfl stages (gates 6..2) ->
//   swizzled re/im exchange -> 2 real reg stages (gates 1,0) -> |amp|^2 ->
//   block reduce over 7 columns -> RED.F32 into out (after memset node).
// ---------------------------------------------------------------------------
__global__ void __launch_bounds__(TPB, 1) sim_kernel(const float* __restrict__ x,
                                                     const float* __restrict__ w,
                                                     float* __restrict__ out) {
    extern __shared__ float dynf[];
    float2* sT1 = (float2*)dynf;            // [1024] (overlaid by staging later)
    float2* sT2 = (float2*)dynf + 1024;     // [1024]
    // staging: column c -> re plane dynf + c*2048, im plane +1024

    __shared__ float2 sv[NQ][2];
    __shared__ int    sFB[NQ];
    __shared__ float2 sRot[NPART];   // (cos b/2, sin b/2) per gate
    __shared__ float2 sE[NPART];     // e^{i gamma_q}
    __shared__ float2 sDR8[8];       // r-bit phase products (gates 9,8,7)
    __shared__ int    sXR[8];

    const int tid  = threadIdx.x;
    const int warp = tid >> 5;
    const int lane = tid & 31;
    const int c    = warp >> 2;        // column slot 0..6
    const int qw   = warp & 3;         // warp-in-quad (h bits 8,9)

    const float RS2  = 0.70710678118654752440f;   // 1/sqrt(2)
    const float WMUL = 0.63245553203367586640f;   // sqrt(2/5)

    if (tid < NQ) {
        // encoding column v_q = Rz(atan(x^2)) * Ry(atan(x)) * H |0>
        const int q = tid;
        float xq = x[q];
        float th = atanf(xq);
        float cc, ss;
        sincosf(0.5f * th, &ss, &cc);
        float a = (cc - ss) * RS2;
        float b = (cc + ss) * RS2;
        float ph = 0.5f * atanf(xq * xq);
        float pc, ps;
        sincosf(ph, &ps, &pc);
        sv[q][0] = make_float2(a * pc, -a * ps);
        sv[q][1] = make_float2(b * pc,  b * ps);

        // f = inverse CNOT-ring permutation on basis bit p=tid
        int y = 1 << tid;
        for (int qq = NQ - 1; qq >= 0; --qq) {
            int cb  = 19 - qq;
            int tb2 = 19 - ((qq + 2) % NQ);
            int tb1 = 19 - ((qq + 1) % NQ);
            if ((y >> cb) & 1) y ^= (1 << tb2);
            if ((y >> cb) & 1) y ^= (1 << tb1);
        }
        sFB[tid] = y;
    }

    if (tid < NPART) {
        // fused variational gate V = Rx(w2)*Rz(w1)*Rx(w0), then ZYZ extract:
        // c = |V00|, s = |V10|, gamma = -(arg V00 + arg V10). Rz(alpha) dropped.
        const int q = tid;
        float w0 = w[3 * q + 0] * WMUL;
        float w1 = w[3 * q + 1] * WMUL;
        float w2 = w[3 * q + 2] * WMUL;
        float c0, s0, c1, s1, c2, s2;
        sincosf(0.5f * w0, &s0, &c0);
        sincosf(0.5f * w1, &s1, &c1);
        sincosf(0.5f * w2, &s2, &c2);
        float2 r00 = make_float2(c0, 0.f), r01 = make_float2(0.f, -s0);
        float2 d0  = make_float2(c1, -s1), d1  = make_float2(c1,  s1);
        float2 A00 = cmul(d0, r00), A01 = cmul(d0, r01);
        float2 A10 = cmul(d1, r01), A11 = cmul(d1, r00);
        float2 m = make_float2(0.f, -s2);
        float2 V00 = cadd(make_float2(c2 * A00.x, c2 * A00.y), cmul(m, A10));
        float2 V10 = cadd(cmul(m, A00), make_float2(c2 * A10.x, c2 * A10.y));
        float cb = sqrtf(V00.x * V00.x + V00.y * V00.y);
        float sb = sqrtf(V10.x * V10.x + V10.y * V10.y);
        sRot[q] = make_float2(cb, sb);
        float g = -(atan2f(V00.y, V00.x) + atan2f(V10.y, V10.x));
        float cg, sg;
        sincosf(g, &sg, &cg);
        sE[q] = make_float2(cg, sg);
    }
    __syncthreads();

    // product tables
    for (int a = tid; a < 1024; a += TPB) {
        float2 p1 = make_float2(1.f, 0.f);
        float2 p2 = make_float2(1.f, 0.f);
#pragma unroll
        for (int q = 0; q < NPART; ++q)
            p1 = cmul(p1, sv[q][(a >> (9 - q)) & 1]);
#pragma unroll
        for (int q = NPART; q < NQ; ++q)
            p2 = cmul(p2, sv[q][(a >> (19 - q)) & 1]);
        sT1[a] = p1;
        sT2[a] = p2;
    }
    if (tid < 8) {
        int v = 0;
#pragma unroll
        for (int i = 0; i < 3; ++i)
            if ((tid >> i) & 1) v ^= sFB[10 + i];   // h bit i -> global bit 10+i
        sXR[tid] = v;
        // r-bit gamma phases: h bit b (b=0..2) carries gate 9-b
        float2 dv = make_float2(1.f, 0.f);
        if (tid & 1) dv = cmul(dv, sE[9]);
        if (tid & 2) dv = cmul(dv, sE[8]);
        if (tid & 4) dv = cmul(dv, sE[7]);
        sDR8[tid] = dv;
    }
    __syncthreads();

    // ---- this quad's column (dummy slots masked via wgt)
    const int lraw = blockIdx.x * CPB + c;
    const float wgt = (lraw < 1024) ? 1.f : 0.f;
    const int l = lraw & 1023;
    int xl = 0;
#pragma unroll
    for (int j = 0; j < 10; ++j)
        if ((l >> j) & 1) xl ^= sFB[j];
    int hx = 0;
#pragma unroll
    for (int p = 0; p < 5; ++p)
        if ((lane >> p) & 1) hx ^= sFB[13 + p];   // h bit 3+p -> global bit 13+p
    if (qw & 1) hx ^= sFB[18];                    // h bit 8
    if (qw & 2) hx ^= sFB[19];                    // h bit 9
    const int xbase = xl ^ hx;

    // thread-constant gamma phase: lane bit p -> gate 6-p; qw bits -> gates 1,0
    float2 tph = make_float2(1.f, 0.f);
    if (lane & 1)  tph = cmul(tph, sE[6]);
    if (lane & 2)  tph = cmul(tph, sE[5]);
    if (lane & 4)  tph = cmul(tph, sE[4]);
    if (lane & 8)  tph = cmul(tph, sE[3]);
    if (lane & 16) tph = cmul(tph, sE[2]);
    if (qw & 1)    tph = cmul(tph, sE[1]);
    if (qw & 2)    tph = cmul(tph, sE[0]);

    // synthesize 8 amps with folded Rz(gamma) phases: h = (qw<<8)|(lane<<3)|r
    float2 a[8];
#pragma unroll
    for (int r = 0; r < 8; ++r) {
        int xx = xbase ^ sXR[r];
        float2 z = cmul(sT1[xx >> 10], sT2[xx & 1023]);
        a[r] = cmul(z, cmul(tph, sDR8[r]));
    }
    __syncthreads();   // all warps done reading tables -> staging may overwrite

    // phase 1: 3 REAL reg stages on h bits 0..2 (gates q = 9,8,7)
#pragma unroll
    for (int b = 0; b < 3; ++b) {
        float2 rot = sRot[9 - b];
#pragma unroll
        for (int g = 0; g < 4; ++g) {
            int lo = g & ((1 << b) - 1);
            int r0 = ((g >> b) << (b + 1)) | lo;
            int r1 = r0 | (1 << b);
            bflyR(a[r0], a[r1], rot.x, rot.y);
        }
    }

    // phase 2: 5 REAL shfl stages on h bits 3..7 (lane bit p, gates q = 6..2)
#pragma unroll
    for (int p = 0; p < 5; ++p) {
        float2 rot = sRot[6 - p];
        const int bitv = (lane >> p) & 1;
        const float cc = rot.x;
        const float so = bitv ? rot.y : -rot.y;
#pragma unroll
        for (int r = 0; r < 8; ++r) {
            float ox = __shfl_xor_sync(0xffffffffu, a[r].x, 1 << p);
            float oy = __shfl_xor_sync(0xffffffffu, a[r].y, 1 << p);
            a[r].x = fmaf(so, ox, cc * a[r].x);
            a[r].y = fmaf(so, oy, cc * a[r].y);
        }
    }

    // exchange: bring h bits 8,9 into register bits (swizzled re/im planes).
    // store: swz((qw<<8)|(lane<<3)|r) = stb ^ r with stb = base ^ lane
    float* sRe = dynf + c * 2048;
    float* sIm = sRe + 1024;
    {
        const int stb = ((qw << 8) | (lane << 3)) ^ lane;
#pragma unroll
        for (int r = 0; r < 8; ++r) {
            sRe[stb ^ r] = a[r].x;
            sIm[stb ^ r] = a[r].y;
        }
    }
    asm volatile("bar.sync %0, %1;" :: "r"(c + 1), "r"(128) : "memory");

    // read mapping h = ((r&3)<<8)|(lane<<3)|(qw<<1)|(r>>2); swz mask = lane
    const int sbase = ((lane << 3) | (qw << 1)) ^ lane;
    int sad[8];
#pragma unroll
    for (int r = 0; r < 8; ++r)
        sad[r] = sbase ^ ((r & 3) << 8) ^ (r >> 2);
#pragma unroll
    for (int r = 0; r < 8; ++r)
        a[r] = make_float2(sRe[sad[r]], sIm[sad[r]]);

    // phase 3: 2 REAL reg stages on h bit 8 (gate 1, r bit0), h bit 9 (gate 0, r bit1)
    {
        float2 rot = sRot[1];
        bflyR(a[0], a[1], rot.x, rot.y);
        bflyR(a[2], a[3], rot.x, rot.y);
        bflyR(a[4], a[5], rot.x, rot.y);
        bflyR(a[6], a[7], rot.x, rot.y);
    }
    {
        float2 rot = sRot[0];
        bflyR(a[0], a[2], rot.x, rot.y);
        bflyR(a[1], a[3], rot.x, rot.y);
        bflyR(a[4], a[6], rot.x, rot.y);
        bflyR(a[5], a[7], rot.x, rot.y);
    }

    // |amp|^2 back to the cached addresses (dummy columns zero-weighted)
#pragma unroll
    for (int r = 0; r < 8; ++r) {
        float p = a[r].x * a[r].x;
        p = fmaf(a[r].y, a[r].y, p);
        sRe[sad[r]] = wgt * p;
    }
    __syncthreads();

    // block reduce over the 7 columns, RED.F32 into out (order-insensitive
    // to ~1e-7; tolerance is 1e-3)
    for (int h = tid; h < 1024; h += TPB) {
        const int ad = swz(h);
        float s = 0.f;
#pragma unroll
        for (int cc = 0; cc < CPB; ++cc)
            s += dynf[cc * 2048 + ad];
        atomicAdd(&out[h], s);
    }
}

extern "C" void kernel_launch(void* const* d_in, const int* in_sizes, int n_in,
                              void* d_out, int out_size) {
    const float* x = (const float*)d_in[0];   // (1, 20) float32
    const float* w = (const float*)d_in[1];   // (60,)  float32
    float* out = (float*)d_out;               // (1, 1024) float32

    cudaMemsetAsync(out, 0, 1024 * sizeof(float));
    const int dynsmem = CPB * 2048 * 4;       // 56 KB (tables overlay staging)
    cudaFuncSetAttribute(sim_kernel, cudaFuncAttributeMaxDynamicSharedMemorySize, dynsmem);
    sim_kernel<<<NB, TPB, dynsmem>>>(x, w, out);
}